// round 15
// baseline (speedup 1.0000x reference)
#include <cuda_runtime.h>
#include <cuda_fp16.h>
#include <cstdint>

#define SEQ 1024
#define DIM 128
#define NG 64

__device__ __half g_qh0[(size_t)NG*SEQ*DIM];
__device__ __half g_qh1[(size_t)NG*SEQ*DIM];
__device__ __half g_kh0[(size_t)NG*SEQ*DIM];
__device__ __half g_kh1[(size_t)NG*SEQ*DIM];
__device__ __half g_vh0[(size_t)NG*SEQ*DIM];
__device__ __half g_oh [(size_t)NG*SEQ*DIM];

// ---------------- helpers ----------------
__device__ __forceinline__ uint32_t s2u(const void* p){
    uint32_t a; asm("{ .reg .u64 t; cvta.to.shared.u64 t,%1; cvt.u32.u64 %0,t; }":"=r"(a):"l"(p)); return a;
}
__device__ __forceinline__ void cpa16(uint32_t d, const void* s){
    asm volatile("cp.async.cg.shared.global [%0],[%1],16;"::"r"(d),"l"(s));
}
#define CPCOMMIT() asm volatile("cp.async.commit_group;":::"memory")
#define CPWAIT0()  asm volatile("cp.async.wait_group 0;":::"memory")

__device__ __forceinline__ void ldm4(uint32_t r[4], uint32_t a){
    asm volatile("ldmatrix.sync.aligned.m8n8.x4.shared.b16 {%0,%1,%2,%3},[%4];"
        :"=r"(r[0]),"=r"(r[1]),"=r"(r[2]),"=r"(r[3]):"r"(a));
}
__device__ __forceinline__ void ldm4t(uint32_t r[4], uint32_t a){
    asm volatile("ldmatrix.sync.aligned.m8n8.x4.trans.shared.b16 {%0,%1,%2,%3},[%4];"
        :"=r"(r[0]),"=r"(r[1]),"=r"(r[2]),"=r"(r[3]):"r"(a));
}
__device__ __forceinline__ void mmaf(float c[4], const uint32_t a[4], uint32_t b0, uint32_t b1){
    asm volatile("mma.sync.aligned.m16n8k16.row.col.f32.f16.f16.f32 "
        "{%0,%1,%2,%3},{%4,%5,%6,%7},{%8,%9},{%0,%1,%2,%3};"
        :"+f"(c[0]),"+f"(c[1]),"+f"(c[2]),"+f"(c[3])
        :"r"(a[0]),"r"(a[1]),"r"(a[2]),"r"(a[3]),"r"(b0),"r"(b1));
}
__device__ __forceinline__ uint32_t pkh(float a, float b){
    __half2 h = __floats2half2_rn(a,b); return *(uint32_t*)&h;
}
__device__ __forceinline__ float fex2(float x){
    x = fmaxf(x, -120.f);
    float xf = floorf(x), f = x - xf;
    float p = fmaf(f, 0.0013333558f, 0.0096181291f);
    p = fmaf(f, p, 0.0555041087f);
    p = fmaf(f, p, 0.2402265070f);
    p = fmaf(f, p, 0.6931471806f);
    p = fmaf(f, p, 1.0f);
    return __int_as_float(((int)xf + 127) << 23) * p;
}
#define SWZH(r,d) ((r)*128 + ((((d)>>3)^((r)&7))<<3) + ((d)&7))

__device__ __forceinline__ void split_store(__half* sm, uint32_t offH, uint32_t offL, float4 t){
    __half2 h01=__floats2half2_rn(t.x,t.y), h23=__floats2half2_rn(t.z,t.w);
    float2 f01=__half22float2(h01), f23=__half22float2(h23);
    __half2 l01=__floats2half2_rn(t.x-f01.x,t.y-f01.y), l23=__floats2half2_rn(t.z-f23.x,t.w-f23.y);
    *(uint32_t*)((char*)sm+offH)  =*(uint32_t*)&h01;
    *(uint32_t*)((char*)sm+offH+4)=*(uint32_t*)&h23;
    *(uint32_t*)((char*)sm+offL)  =*(uint32_t*)&l01;
    *(uint32_t*)((char*)sm+offL+4)=*(uint32_t*)&l23;
}

// ================= Kernel 1a: Q/K projections, 64-row tiles (R9, best) ======
#define PROJQK_SMEM 98304
__global__ void __launch_bounds__(256,2) proj_qk_kernel(
    const float* __restrict__ Xq, const float* __restrict__ Xk,
    const float* __restrict__ Wq, const float* __restrict__ Wk)
{
    extern __shared__ __half sm[];
    const uint32_t sb=s2u(sm);
    const int z=blockIdx.z, mat=z>>3, bm=z&7, m=bm&3;
    const float* X=(mat? Xk:Xq)+(size_t)bm*SEQ*DIM;
    const float* W=(mat? Wk:Wq)+(size_t)m*DIM*(8*DIM);
    const int tid=threadIdx.x, warp=tid>>5, lane=tid&31;
    const int bx=blockIdx.x, by=blockIdx.y;
    const int wm=warp&3, wn=warp>>2;
    const int lr=(lane&7)+((lane>>3)&1)*8;
    const int ldd=((lane>>4)&1)*8;

#pragma unroll
    for(int i=0;i<8;i++){
        int idx=tid+i*256, row=idx>>5, c4=(idx&31)*4;
        float4 xv=*(const float4*)(X+(size_t)(by*64+row)*DIM+c4);
        uint32_t xo=2*SWZH(row,c4);
        split_store(sm, xo, 16384+xo, xv);
    }
#pragma unroll
    for(int i=0;i<16;i++){
        int idx=tid+i*256, row=idx>>5, c4=(idx&31)*4;
        float4 wv=*(const float4*)(W+(size_t)row*(8*DIM)+bx*128+c4);
        uint32_t wo=2*SWZH(row,c4);
        split_store(sm, 32768+wo, 65536+wo, wv);
    }
    __syncthreads();

    float acc[8][4];
#pragma unroll
    for(int j=0;j<8;j++)
#pragma unroll
        for(int p2=0;p2<4;p2++) acc[j][p2]=0.f;

#pragma unroll
    for(int kc=0;kc<8;kc++){
        uint32_t ah[4], al[4];
        ldm4(ah, sb+2*(SWZH(wm*16+lr, kc*16+ldd)));
        ldm4(al, sb+2*(8192+SWZH(wm*16+lr, kc*16+ldd)));
#pragma unroll
        for(int np=0;np<4;np++){
            uint32_t wh[4], wl[4];
            ldm4t(wh, sb+2*(16384+SWZH(kc*16+lr, wn*64+np*16+ldd)));
            ldm4t(wl, sb+2*(32768+SWZH(kc*16+lr, wn*64+np*16+ldd)));
            mmaf(acc[2*np],ah,wh[0],wh[1]); mmaf(acc[2*np+1],ah,wh[2],wh[3]);
            mmaf(acc[2*np],ah,wl[0],wl[1]); mmaf(acc[2*np+1],ah,wl[2],wl[3]);
            mmaf(acc[2*np],al,wh[0],wh[1]); mmaf(acc[2*np+1],al,wh[2],wh[3]);
        }
    }

    const int g=bm*8+bx;
    __half* d0 = mat? g_kh0 : g_qh0;
    __half* d1 = mat? g_kh1 : g_qh1;
    const float sc = mat? 1.f : 0.12753102001968606f;   // log2(e)/sqrt(128)
    const int rbase=by*64+wm*16+(lane>>2);
    const int dbase=wn*64+2*(lane&3);
#pragma unroll
    for(int j=0;j<8;j++)
#pragma unroll
        for(int hr=0;hr<2;hr++){
            int r=rbase+hr*8, d=dbase+j*8;
            float x0=acc[j][2*hr]*sc, x1=acc[j][2*hr+1]*sc;
            __half2 h=__floats2half2_rn(x0,x1);
            size_t off=((size_t)(g*SEQ)+r)*DIM+d;
            *(__half2*)(d0+off)=h;
            float2 hf=__half22float2(h);
            *(__half2*)(d1+off)=__floats2half2_rn(x0-hf.x,x1-hf.y);
        }
}

// ================= Kernel 1b: V projection, hh-only, 64-row tiles (R9) ======
#define PROJV_SMEM 49152
__global__ void __launch_bounds__(256,2) proj_v_kernel(
    const float* __restrict__ Xv, const float* __restrict__ Wv)
{
    extern __shared__ __half sm[];
    const uint32_t sb=s2u(sm);
    const int bm=blockIdx.z, m=bm&3;
    const float* X=Xv+(size_t)bm*SEQ*DIM;
    const float* W=Wv+(size_t)m*DIM*(8*DIM);
    const int tid=threadIdx.x, warp=tid>>5, lane=tid&31;
    const int bx=blockIdx.x, by=blockIdx.y;
    const int wm=warp&3, wn=warp>>2;
    const int lr=(lane&7)+((lane>>3)&1)*8;
    const int ldd=((lane>>4)&1)*8;

#pragma unroll
    for(int i=0;i<8;i++){
        int idx=tid+i*256, row=idx>>5, c4=(idx&31)*4;
        float4 t=*(const float4*)(X+(size_t)(by*64+row)*DIM+c4);
        __half2 h01=__floats2half2_rn(t.x,t.y), h23=__floats2half2_rn(t.z,t.w);
        uint32_t xo=2*SWZH(row,c4);
        *(uint32_t*)((char*)sm+xo)=*(uint32_t*)&h01; *(uint32_t*)((char*)sm+xo+4)=*(uint32_t*)&h23;
    }
#pragma unroll
    for(int i=0;i<16;i++){
        int idx=tid+i*256, row=idx>>5, c4=(idx&31)*4;
        float4 t=*(const float4*)(W+(size_t)row*(8*DIM)+bx*128+c4);
        __half2 h01=__floats2half2_rn(t.x,t.y), h23=__floats2half2_rn(t.z,t.w);
        uint32_t wo=2*SWZH(row,c4);
        *(uint32_t*)((char*)sm+16384+wo)=*(uint32_t*)&h01; *(uint32_t*)((char*)sm+16384+wo+4)=*(uint32_t*)&h23;
    }
    __syncthreads();

    float acc[8][4];
#pragma unroll
    for(int j=0;j<8;j++)
#pragma unroll
        for(int p2=0;p2<4;p2++) acc[j][p2]=0.f;

#pragma unroll
    for(int kc=0;kc<8;kc++){
        uint32_t ah[4];
        ldm4(ah, sb+2*(SWZH(wm*16+lr, kc*16+ldd)));
#pragma unroll
        for(int np=0;np<4;np++){
            uint32_t wh[4];
            ldm4t(wh, sb+2*(8192+SWZH(kc*16+lr, wn*64+np*16+ldd)));
            mmaf(acc[2*np],ah,wh[0],wh[1]); mmaf(acc[2*np+1],ah,wh[2],wh[3]);
        }
    }

    const int g=bm*8+bx;
    const int rbase=by*64+wm*16+(lane>>2);
    const int dbase=wn*64+2*(lane&3);
#pragma unroll
    for(int j=0;j<8;j++)
#pragma unroll
        for(int hr=0;hr<2;hr++){
            int r=rbase+hr*8, d=dbase+j*8;
            size_t off=((size_t)(g*SEQ)+r)*DIM+d;
            *(__half2*)(g_vh0+off)=__floats2half2_rn(acc[j][2*hr],acc[j][2*hr+1]);
        }
}

// ================= Kernel 2: flash attention, 64KB smem, 3 CTAs/SM ==========
// half-index map: Kh[b]=b*8192 | Kl=16384 (single) | Vh=24576 (single)
// Q staged pre-loop: Qh at 16384, Ql at 24576 (consumed before loads).
#define ATTN_SMEM 65536

__device__ __forceinline__ void load_kh(uint32_t sb, size_t gbase, int t, int buf, int tid){
#pragma unroll
    for(int i=0;i<8;i++){
        int idx=tid+i*128, row=idx>>4, ch=idx&15;
        cpa16(sb+2*(buf*8192+SWZH(row,ch*8)),
              g_kh0+gbase+(size_t)(t*64+row)*DIM+ch*8);
    }
}
__device__ __forceinline__ void load_kl(uint32_t sb, size_t gbase, int t, int tid){
#pragma unroll
    for(int i=0;i<8;i++){
        int idx=tid+i*128, row=idx>>4, ch=idx&15;
        cpa16(sb+2*(16384+SWZH(row,ch*8)),
              g_kh1+gbase+(size_t)(t*64+row)*DIM+ch*8);
    }
}
__device__ __forceinline__ void load_vh(uint32_t sb, size_t gbase, int t, int tid){
#pragma unroll
    for(int i=0;i<8;i++){
        int idx=tid+i*128, row=idx>>4, ch=idx&15;
        cpa16(sb+2*(24576+SWZH(row,ch*8)),
              g_vh0+gbase+(size_t)(t*64+row)*DIM+ch*8);
    }
}

__global__ void __launch_bounds__(128,3) attn_kernel()
{
    extern __shared__ __half sm[];
    const uint32_t sb=s2u(sm);
    const int tid=threadIdx.x, warp=tid>>5, lane=tid&31;
    const int g=blockIdx.y, qt=blockIdx.x;
    const size_t gbase=(size_t)g*SEQ*DIM;
    const int lr=(lane&7)+((lane>>3)&1)*8;
    const int ldd=((lane>>4)&1)*8;

    // stage Q: hi at 16384, lo at 24576
#pragma unroll
    for(int i=0;i<16;i++){
        int idx=tid+i*128, arr=idx>>10, rem=idx&1023, row=rem>>4, ch=rem&15;
        const __half* src=(arr? g_qh1:g_qh0)+gbase+(size_t)(qt*64+row)*DIM+ch*8;
        cpa16(sb+2*((arr?24576:16384)+SWZH(row,ch*8)), src);
    }
    CPCOMMIT(); CPWAIT0();
    __syncthreads();
    uint32_t qah[8][4], qal[8][4];
#pragma unroll
    for(int kc=0;kc<8;kc++){
        ldm4(qah[kc], sb+2*(16384+SWZH(warp*16+lr, kc*16+ldd)));
        ldm4(qal[kc], sb+2*(24576+SWZH(warp*16+lr, kc*16+ldd)));
    }
    __syncthreads();   // Q consumed; loads may overwrite Kl/Vh regions

    load_kh(sb,gbase,0,0,tid); load_kl(sb,gbase,0,tid); load_vh(sb,gbase,0,tid); CPCOMMIT();
    load_kh(sb,gbase,1,1,tid); CPCOMMIT();

    float o[16][4];
#pragma unroll
    for(int i=0;i<16;i++)
#pragma unroll
        for(int j2=0;j2<4;j2++) o[i][j2]=0.f;
    float mA=-1e30f, mB=-1e30f, lA=0.f, lB=0.f;

    for(int t=0;t<16;t++){
        CPWAIT0();
        __syncthreads();
        const uint32_t KHB=(t&1)*8192, KLB=16384, VHB=24576;

        float c[8][4];
#pragma unroll
        for(int j=0;j<8;j++)
#pragma unroll
            for(int i2=0;i2<4;i2++) c[j][i2]=0.f;
#pragma unroll
        for(int kc=0;kc<8;kc++){
#pragma unroll
            for(int np=0;np<4;np++){
                uint32_t kh[4],kl[4];
                ldm4(kh, sb+2*(KHB+SWZH(np*16+lr, kc*16+ldd)));
                ldm4(kl, sb+2*(KLB+SWZH(np*16+lr, kc*16+ldd)));
                mmaf(c[2*np],qah[kc],kh[0],kh[2]); mmaf(c[2*np+1],qah[kc],kh[1],kh[3]);
                mmaf(c[2*np],qah[kc],kl[0],kl[2]); mmaf(c[2*np+1],qah[kc],kl[1],kl[3]);
                mmaf(c[2*np],qal[kc],kh[0],kh[2]); mmaf(c[2*np+1],qal[kc],kh[1],kh[3]);
            }
        }
        __syncthreads();                    // all warps done reading Kl(t), Kh(t)
        if(t+1<16) load_kl(sb,gbase,t+1,tid);
        if(t+2<16) load_kh(sb,gbase,t+2,t&1,tid);
        CPCOMMIT();

        float tA=-1e30f, tB=-1e30f;
#pragma unroll
        for(int j=0;j<8;j++){
            tA=fmaxf(tA,fmaxf(c[j][0],c[j][1]));
            tB=fmaxf(tB,fmaxf(c[j][2],c[j][3]));
        }
        tA=fmaxf(tA,__shfl_xor_sync(0xffffffffu,tA,1));
        tA=fmaxf(tA,__shfl_xor_sync(0xffffffffu,tA,2));
        tB=fmaxf(tB,__shfl_xor_sync(0xffffffffu,tB,1));
        tB=fmaxf(tB,__shfl_xor_sync(0xffffffffu,tB,2));
        float mnA=fmaxf(mA,tA), mnB=fmaxf(mB,tB);
        float cA=fex2(mA-mnA), cB=fex2(mB-mnB);
        mA=mnA; mB=mnB;
        uint32_t pa[8], pb[8];
        float sA=0.f, sB=0.f;
#pragma unroll
        for(int j=0;j<8;j++){
            float p0=fex2(c[j][0]-mnA), p1=fex2(c[j][1]-mnA);
            float p2=fex2(c[j][2]-mnB), p3=fex2(c[j][3]-mnB);
            sA+=p0+p1; sB+=p2+p3;
            pa[j]=pkh(p0,p1); pb[j]=pkh(p2,p3);
        }
        lA=lA*cA+sA; lB=lB*cB+sB;
        if(cA!=1.f){
#pragma unroll
            for(int dt=0;dt<16;dt++){ o[dt][0]*=cA; o[dt][1]*=cA; }
        }
        if(cB!=1.f){
#pragma unroll
            for(int dt=0;dt<16;dt++){ o[dt][2]*=cB; o[dt][3]*=cB; }
        }

#pragma unroll
        for(int kc=0;kc<4;kc++){
            uint32_t a4[4]={pa[2*kc],pb[2*kc],pa[2*kc+1],pb[2*kc+1]};
#pragma unroll
            for(int dp=0;dp<8;dp++){
                uint32_t vh[4];
                ldm4t(vh, sb+2*(VHB+SWZH(kc*16+lr, dp*16+ldd)));
                mmaf(o[2*dp],a4,vh[0],vh[1]); mmaf(o[2*dp+1],a4,vh[2],vh[3]);
            }
        }
        __syncthreads();                    // all warps done reading Vh(t)
        if(t+1<16){ load_vh(sb,gbase,t+1,tid); CPCOMMIT(); }
    }

    lA+=__shfl_xor_sync(0xffffffffu,lA,1); lA+=__shfl_xor_sync(0xffffffffu,lA,2);
    lB+=__shfl_xor_sync(0xffffffffu,lB,1); lB+=__shfl_xor_sync(0xffffffffu,lB,2);
    float iA=1.f/lA, iB=1.f/lB;
    int rA=qt*64+warp*16+(lane>>2), rB=rA+8, dc=2*(lane&3);
    __half* obase=g_oh+gbase;
#pragma unroll
    for(int dt=0;dt<16;dt++){
        *(__half2*)(obase+(size_t)rA*DIM+dt*8+dc)=__floats2half2_rn(o[dt][0]*iA,o[dt][1]*iA);
        *(__half2*)(obase+(size_t)rB*DIM+dt*8+dc)=__floats2half2_rn(o[dt][2]*iB,o[dt][3]*iB);
    }
}

// ================= Kernel 3: head-mean + residual ===========================
__global__ void __launch_bounds__(256) reduce_kernel(const float* __restrict__ q, float* __restrict__ out)
{
    int i4=blockIdx.x*256+threadIdx.x;
    int bm=i4>>15, r4=i4&32767;
    float sx=0,sy=0,sz=0,sw=0;
#pragma unroll
    for(int h=0;h<8;h++){
        uint2 v=*(const uint2*)(g_oh+((size_t)(bm*8+h))*131072+(size_t)r4*4);
        __half2 a=*(__half2*)&v.x, b=*(__half2*)&v.y;
        float2 fa=__half22float2(a), fb=__half22float2(b);
        sx+=fa.x; sy+=fa.y; sz+=fb.x; sw+=fb.y;
    }
    float4 qv=((const float4*)q)[i4];
    ((float4*)out)[i4]=make_float4(qv.x+0.125f*sx,qv.y+0.125f*sy,qv.z+0.125f*sz,qv.w+0.125f*sw);
}

extern "C" void kernel_launch(void* const* d_in, const int* in_sizes, int n_in,
                              void* d_out, int out_size)
{
    const float *q=(const float*)d_in[0], *k=(const float*)d_in[1], *v=(const float*)d_in[2];
    const float *Wq=(const float*)d_in[3], *Wk=(const float*)d_in[4], *Wv=(const float*)d_in[5];
    float* out=(float*)d_out;
    cudaFuncSetAttribute(proj_qk_kernel, cudaFuncAttributeMaxDynamicSharedMemorySize, PROJQK_SMEM);
    cudaFuncSetAttribute(proj_v_kernel, cudaFuncAttributeMaxDynamicSharedMemorySize, PROJV_SMEM);
    cudaFuncSetAttribute(attn_kernel, cudaFuncAttributeMaxDynamicSharedMemorySize, ATTN_SMEM);
    proj_qk_kernel<<<dim3(8,16,16),256,PROJQK_SMEM>>>(q,k,Wq,Wk);
    proj_v_kernel <<<dim3(8,16,8),256,PROJV_SMEM>>>(v,Wv);
    attn_kernel<<<dim3(16,64),128,ATTN_SMEM>>>();
    reduce_kernel<<<1024,256>>>(q,out);
}

// round 16
// speedup vs baseline: 1.1528x; 1.1528x over previous
#include <cuda_runtime.h>
#include <cuda_fp16.h>
#include <cstdint>

#define SEQ 1024
#define DIM 128
#define NG 64

__device__ __half g_qh0[(size_t)NG*SEQ*DIM];
__device__ __half g_qh1[(size_t)NG*SEQ*DIM];
__device__ __half g_kh0[(size_t)NG*SEQ*DIM];
__device__ __half g_kh1[(size_t)NG*SEQ*DIM];
__device__ __half g_vh0[(size_t)NG*SEQ*DIM];
__device__ __half g_oh [(size_t)NG*SEQ*DIM];

// ---------------- helpers ----------------
__device__ __forceinline__ uint32_t s2u(const void* p){
    uint32_t a; asm("{ .reg .u64 t; cvta.to.shared.u64 t,%1; cvt.u32.u64 %0,t; }":"=r"(a):"l"(p)); return a;
}
__device__ __forceinline__ void cpa16(uint32_t d, const void* s){
    asm volatile("cp.async.cg.shared.global [%0],[%1],16;"::"r"(d),"l"(s));
}
#define CPCOMMIT() asm volatile("cp.async.commit_group;":::"memory")
#define CPWAIT1()  asm volatile("cp.async.wait_group 1;":::"memory")
#define CPWAIT0()  asm volatile("cp.async.wait_group 0;":::"memory")

__device__ __forceinline__ void ldm4(uint32_t r[4], uint32_t a){
    asm volatile("ldmatrix.sync.aligned.m8n8.x4.shared.b16 {%0,%1,%2,%3},[%4];"
        :"=r"(r[0]),"=r"(r[1]),"=r"(r[2]),"=r"(r[3]):"r"(a));
}
__device__ __forceinline__ void ldm4t(uint32_t r[4], uint32_t a){
    asm volatile("ldmatrix.sync.aligned.m8n8.x4.trans.shared.b16 {%0,%1,%2,%3},[%4];"
        :"=r"(r[0]),"=r"(r[1]),"=r"(r[2]),"=r"(r[3]):"r"(a));
}
__device__ __forceinline__ void mmaf(float c[4], const uint32_t a[4], uint32_t b0, uint32_t b1){
    asm volatile("mma.sync.aligned.m16n8k16.row.col.f32.f16.f16.f32 "
        "{%0,%1,%2,%3},{%4,%5,%6,%7},{%8,%9},{%0,%1,%2,%3};"
        :"+f"(c[0]),"+f"(c[1]),"+f"(c[2]),"+f"(c[3])
        :"r"(a[0]),"r"(a[1]),"r"(a[2]),"r"(a[3]),"r"(b0),"r"(b1));
}
__device__ __forceinline__ uint32_t pkh(float a, float b){
    __half2 h = __floats2half2_rn(a,b); return *(uint32_t*)&h;
}
__device__ __forceinline__ float fex2(float x){
    x = fmaxf(x, -120.f);
    float xf = floorf(x), f = x - xf;
    float p = fmaf(f, 0.0013333558f, 0.0096181291f);
    p = fmaf(f, p, 0.0555041087f);
    p = fmaf(f, p, 0.2402265070f);
    p = fmaf(f, p, 0.6931471806f);
    p = fmaf(f, p, 1.0f);
    return __int_as_float(((int)xf + 127) << 23) * p;
}
// swizzle for 256B rows (128 halves/row)
#define SWZH(r,d)  ((r)*128 + ((((d)>>3)^((r)&7))<<3) + ((d)&7))
// swizzle for 128B rows (64 halves/row): 8 segments of 16B, XOR by row&7
#define SWZ64H(r,d) ((r)*64 + (((((d)>>3)^((r)&7))&7)<<3) + ((d)&7))

__device__ __forceinline__ void split_store_at(__half* sm, uint32_t offH, uint32_t offL, float4 t){
    __half2 h01=__floats2half2_rn(t.x,t.y), h23=__floats2half2_rn(t.z,t.w);
    float2 f01=__half22float2(h01), f23=__half22float2(h23);
    __half2 l01=__floats2half2_rn(t.x-f01.x,t.y-f01.y), l23=__floats2half2_rn(t.z-f23.x,t.w-f23.y);
    *(uint32_t*)((char*)sm+offH)  =*(uint32_t*)&h01;
    *(uint32_t*)((char*)sm+offH+4)=*(uint32_t*)&h23;
    *(uint32_t*)((char*)sm+offL)  =*(uint32_t*)&l01;
    *(uint32_t*)((char*)sm+offL+4)=*(uint32_t*)&l23;
}
__device__ __forceinline__ void hi_store_at(__half* sm, uint32_t offH, float4 t){
    __half2 h01=__floats2half2_rn(t.x,t.y), h23=__floats2half2_rn(t.z,t.w);
    *(uint32_t*)((char*)sm+offH)  =*(uint32_t*)&h01;
    *(uint32_t*)((char*)sm+offH+4)=*(uint32_t*)&h23;
}

// ================= Kernel 1: merged projections, 128x128 tile, K-chunked ====
// Per chunk (ch=0,1): X[128 rows x 64 k] hi/lo + W[64 k x 128 e] hi/lo.
// smem byte map: XH 0 | XL 16384 | WH 32768 | WL 49152   (64 KB -> 2 CTAs/SM)
// z: 0..7 = Q (3-combo), 8..15 = K (3-combo), 16..23 = V (hh-only)
#define PROJ_SMEM 65536
__global__ void __launch_bounds__(256,2) proj_kernel(
    const float* __restrict__ Xq, const float* __restrict__ Xk, const float* __restrict__ Xv,
    const float* __restrict__ Wq, const float* __restrict__ Wk, const float* __restrict__ Wv)
{
    extern __shared__ __half sm[];
    const uint32_t sb=s2u(sm);
    const int z=blockIdx.z, mat=z>>3, bm=z&7, m=bm&3;
    const bool isV=(mat==2);
    const float* X=(mat==0?Xq:mat==1?Xk:Xv)+(size_t)bm*SEQ*DIM;
    const float* W=(mat==0?Wq:mat==1?Wk:Wv)+(size_t)m*DIM*(8*DIM);
    const int tid=threadIdx.x, warp=tid>>5, lane=tid&31;
    const int bx=blockIdx.x, by=blockIdx.y;      // bx = head/e-tile, by = s-tile
    const int wm=warp&3, wn=warp>>2;             // 32-row group, 64-col group
    const int lr=(lane&7)+((lane>>3)&1)*8;
    const int ldd=((lane>>4)&1)*8;

    float acc[2][8][4];
#pragma unroll
    for(int i=0;i<2;i++)
#pragma unroll
        for(int j=0;j<8;j++)
#pragma unroll
            for(int p2=0;p2<4;p2++) acc[i][j][p2]=0.f;

#pragma unroll
    for(int ch=0;ch<2;ch++){
        __syncthreads();   // previous chunk MMAs done before overwrite
        // X chunk: 128 rows x 64 floats -> 2048 float4
#pragma unroll
        for(int i=0;i<8;i++){
            int idx=tid+i*256, row=idx>>4, c4=(idx&15)*4;
            float4 xv=*(const float4*)(X+(size_t)(by*128+row)*DIM+ch*64+c4);
            uint32_t off=2*SWZ64H(row,c4);
            if(isV) hi_store_at(sm, off, xv);
            else    split_store_at(sm, off, 16384+off, xv);
        }
        // W chunk: 64 k-rows x 128 e-floats -> 2048 float4
#pragma unroll
        for(int i=0;i<8;i++){
            int idx=tid+i*256, row=idx>>5, c4=(idx&31)*4;
            float4 wv=*(const float4*)(W+(size_t)(ch*64+row)*(8*DIM)+bx*128+c4);
            uint32_t off=2*SWZH(row,c4);
            if(isV) hi_store_at(sm, 32768+off, wv);
            else    split_store_at(sm, 32768+off, 49152+off, wv);
        }
        __syncthreads();

#pragma unroll
        for(int kc=0;kc<4;kc++){
            uint32_t ah[2][4], al[2][4];
#pragma unroll
            for(int i=0;i<2;i++){
                ldm4(ah[i], sb+2*SWZ64H(wm*32+i*16+lr, kc*16+ldd));
                if(!isV) ldm4(al[i], sb+16384+2*SWZ64H(wm*32+i*16+lr, kc*16+ldd));
            }
#pragma unroll
            for(int np=0;np<4;np++){
                uint32_t wh[4], wl[4];
                ldm4t(wh, sb+32768+2*SWZH(kc*16+lr, wn*64+np*16+ldd));
#pragma unroll
                for(int i=0;i<2;i++){
                    mmaf(acc[i][2*np],ah[i],wh[0],wh[1]); mmaf(acc[i][2*np+1],ah[i],wh[2],wh[3]);
                }
                if(!isV){
                    ldm4t(wl, sb+49152+2*SWZH(kc*16+lr, wn*64+np*16+ldd));
#pragma unroll
                    for(int i=0;i<2;i++){
                        mmaf(acc[i][2*np],ah[i],wl[0],wl[1]); mmaf(acc[i][2*np+1],ah[i],wl[2],wl[3]);
                        mmaf(acc[i][2*np],al[i],wh[0],wh[1]); mmaf(acc[i][2*np+1],al[i],wh[2],wh[3]);
                    }
                }
            }
        }
    }

    // epilogue: fp32 acc -> fp16 hi/lo (V: hi only)
    const int g=bm*8+bx;
    __half *d0, *d1; float sc;
    if(mat==0){ d0=g_qh0; d1=g_qh1; sc=0.12753102001968606f; }   // log2(e)/sqrt(128)
    else if(mat==1){ d0=g_kh0; d1=g_kh1; sc=1.f; }
    else { d0=g_vh0; d1=0; sc=1.f; }
    const int rbase=by*128+wm*32+(lane>>2);
    const int dbase=wn*64+2*(lane&3);
#pragma unroll
    for(int i=0;i<2;i++)
#pragma unroll
        for(int j=0;j<8;j++)
#pragma unroll
            for(int hr=0;hr<2;hr++){
                int r=rbase+i*16+hr*8, d=dbase+j*8;
                float x0=acc[i][j][2*hr]*sc, x1=acc[i][j][2*hr+1]*sc;
                __half2 h=__floats2half2_rn(x0,x1);
                size_t off=((size_t)(g*SEQ)+r)*DIM+d;
                *(__half2*)(d0+off)=h;
                if(d1){
                    float2 hf=__half22float2(h);
                    *(__half2*)(d1+off)=__floats2half2_rn(x0-hf.x,x1-hf.y);
                }
            }
}

// ================= Kernel 2: flash attention, Br=64, 128 thr, 2 CTAs/SM (R9)
#define ATTN_SMEM 98304

__device__ __forceinline__ void load_kv(uint32_t sb, size_t gbase, int t, int buf, int tid){
#pragma unroll
    for(int i=0;i<24;i++){
        int idx=tid+i*128, arr=idx>>10, rem=idx&1023, row=rem>>4, ch=rem&15;
        const __half* src;
        if(arr==0) src=g_kh0; else if(arr==1) src=g_kh1; else src=g_vh0;
        src += gbase+(size_t)(t*64+row)*DIM+ch*8;
        uint32_t dst=sb+2*(buf*24576+arr*8192+SWZH(row,ch*8));
        cpa16(dst,src);
    }
}

__global__ void __launch_bounds__(128,2) attn_kernel()
{
    extern __shared__ __half sm[];
    const uint32_t sb=s2u(sm);
    const int tid=threadIdx.x, warp=tid>>5, lane=tid&31;
    const int g=blockIdx.y, qt=blockIdx.x;
    const size_t gbase=(size_t)g*SEQ*DIM;
    const int lr=(lane&7)+((lane>>3)&1)*8;
    const int ldd=((lane>>4)&1)*8;

#pragma unroll
    for(int i=0;i<16;i++){
        int idx=tid+i*128, arr=idx>>10, rem=idx&1023, row=rem>>4, ch=rem&15;
        const __half* src=(arr? g_qh1:g_qh0)+gbase+(size_t)(qt*64+row)*DIM+ch*8;
        cpa16(sb+2*((arr?8192:0)+SWZH(row,ch*8)), src);
    }
    CPCOMMIT(); CPWAIT0();
    __syncthreads();
    uint32_t qah[8][4], qal[8][4];
#pragma unroll
    for(int kc=0;kc<8;kc++){
        ldm4(qah[kc], sb+2*(SWZH(warp*16+lr, kc*16+ldd)));
        ldm4(qal[kc], sb+2*(8192+SWZH(warp*16+lr, kc*16+ldd)));
    }
    __syncthreads();   // Q consumed; loads may overwrite

    load_kv(sb,gbase,0,0,tid); CPCOMMIT();
    load_kv(sb,gbase,1,1,tid); CPCOMMIT();

    float o[16][4];
#pragma unroll
    for(int i=0;i<16;i++)
#pragma unroll
        for(int j2=0;j2<4;j2++) o[i][j2]=0.f;
    float mA=-1e30f, mB=-1e30f, lA=0.f, lB=0.f;

    for(int t=0;t<16;t++){
        if(t<15) CPWAIT1(); else CPWAIT0();
        __syncthreads();
        const uint32_t KHB=(t&1)*24576, KLB=KHB+8192, VHB=KHB+16384;

        float c[8][4];
#pragma unroll
        for(int j=0;j<8;j++)
#pragma unroll
            for(int i2=0;i2<4;i2++) c[j][i2]=0.f;
#pragma unroll
        for(int kc=0;kc<8;kc++){
#pragma unroll
            for(int np=0;np<4;np++){
                uint32_t kh[4],kl[4];
                ldm4(kh, sb+2*(KHB+SWZH(np*16+lr, kc*16+ldd)));
                ldm4(kl, sb+2*(KLB+SWZH(np*16+lr, kc*16+ldd)));
                mmaf(c[2*np],qah[kc],kh[0],kh[2]); mmaf(c[2*np+1],qah[kc],kh[1],kh[3]);
                mmaf(c[2*np],qah[kc],kl[0],kl[2]); mmaf(c[2*np+1],qah[kc],kl[1],kl[3]);
                mmaf(c[2*np],qal[kc],kh[0],kh[2]); mmaf(c[2*np+1],qal[kc],kh[1],kh[3]);
            }
        }

        float tA=-1e30f, tB=-1e30f;
#pragma unroll
        for(int j=0;j<8;j++){
            tA=fmaxf(tA,fmaxf(c[j][0],c[j][1]));
            tB=fmaxf(tB,fmaxf(c[j][2],c[j][3]));
        }
        tA=fmaxf(tA,__shfl_xor_sync(0xffffffffu,tA,1));
        tA=fmaxf(tA,__shfl_xor_sync(0xffffffffu,tA,2));
        tB=fmaxf(tB,__shfl_xor_sync(0xffffffffu,tB,1));
        tB=fmaxf(tB,__shfl_xor_sync(0xffffffffu,tB,2));
        float mnA=fmaxf(mA,tA), mnB=fmaxf(mB,tB);
        float cA=fex2(mA-mnA), cB=fex2(mB-mnB);
        mA=mnA; mB=mnB;
        uint32_t pa[8], pb[8];
        float sA=0.f, sB=0.f;
#pragma unroll
        for(int j=0;j<8;j++){
            float p0=fex2(c[j][0]-mnA), p1=fex2(c[j][1]-mnA);
            float p2=fex2(c[j][2]-mnB), p3=fex2(c[j][3]-mnB);
            sA+=p0+p1; sB+=p2+p3;
            pa[j]=pkh(p0,p1); pb[j]=pkh(p2,p3);
        }
        lA=lA*cA+sA; lB=lB*cB+sB;
        if(cA!=1.f){
#pragma unroll
            for(int dt=0;dt<16;dt++){ o[dt][0]*=cA; o[dt][1]*=cA; }
        }
        if(cB!=1.f){
#pragma unroll
            for(int dt=0;dt<16;dt++){ o[dt][2]*=cB; o[dt][3]*=cB; }
        }

#pragma unroll
        for(int kc=0;kc<4;kc++){
            uint32_t a4[4]={pa[2*kc],pb[2*kc],pa[2*kc+1],pb[2*kc+1]};
#pragma unroll
            for(int dp=0;dp<8;dp++){
                uint32_t vh[4];
                ldm4t(vh, sb+2*(VHB+SWZH(kc*16+lr, dp*16+ldd)));
                mmaf(o[2*dp],a4,vh[0],vh[1]); mmaf(o[2*dp+1],a4,vh[2],vh[3]);
            }
        }
        __syncthreads();
        if(t+2<16){ load_kv(sb,gbase,t+2,t&1,tid); CPCOMMIT(); }
    }

    lA+=__shfl_xor_sync(0xffffffffu,lA,1); lA+=__shfl_xor_sync(0xffffffffu,lA,2);
    lB+=__shfl_xor_sync(0xffffffffu,lB,1); lB+=__shfl_xor_sync(0xffffffffu,lB,2);
    float iA=1.f/lA, iB=1.f/lB;
    int rA=qt*64+warp*16+(lane>>2), rB=rA+8, dc=2*(lane&3);
    __half* obase=g_oh+gbase;
#pragma unroll
    for(int dt=0;dt<16;dt++){
        *(__half2*)(obase+(size_t)rA*DIM+dt*8+dc)=__floats2half2_rn(o[dt][0]*iA,o[dt][1]*iA);
        *(__half2*)(obase+(size_t)rB*DIM+dt*8+dc)=__floats2half2_rn(o[dt][2]*iB,o[dt][3]*iB);
    }
}

// ================= Kernel 3: head-mean + residual ===========================
__global__ void __launch_bounds__(256) reduce_kernel(const float* __restrict__ q, float* __restrict__ out)
{
    int i4=blockIdx.x*256+threadIdx.x;
    int bm=i4>>15, r4=i4&32767;
    float sx=0,sy=0,sz=0,sw=0;
#pragma unroll
    for(int h=0;h<8;h++){
        uint2 v=*(const uint2*)(g_oh+((size_t)(bm*8+h))*131072+(size_t)r4*4);
        __half2 a=*(__half2*)&v.x, b=*(__half2*)&v.y;
        float2 fa=__half22float2(a), fb=__half22float2(b);
        sx+=fa.x; sy+=fa.y; sz+=fb.x; sw+=fb.y;
    }
    float4 qv=((const float4*)q)[i4];
    ((float4*)out)[i4]=make_float4(qv.x+0.125f*sx,qv.y+0.125f*sy,qv.z+0.125f*sz,qv.w+0.125f*sw);
}

extern "C" void kernel_launch(void* const* d_in, const int* in_sizes, int n_in,
                              void* d_out, int out_size)
{
    const float *q=(const float*)d_in[0], *k=(const float*)d_in[1], *v=(const float*)d_in[2];
    const float *Wq=(const float*)d_in[3], *Wk=(const float*)d_in[4], *Wv=(const float*)d_in[5];
    float* out=(float*)d_out;
    cudaFuncSetAttribute(proj_kernel, cudaFuncAttributeMaxDynamicSharedMemorySize, PROJ_SMEM);
    cudaFuncSetAttribute(attn_kernel, cudaFuncAttributeMaxDynamicSharedMemorySize, ATTN_SMEM);
    proj_kernel<<<dim3(8,8,24),256,PROJ_SMEM>>>(q,k,v,Wq,Wk,Wv);
    attn_kernel<<<dim3(16,64),128,ATTN_SMEM>>>();
    reduce_kernel<<<1024,256>>>(q,out);
}

// round 17
// speedup vs baseline: 1.2822x; 1.1123x over previous
#include <cuda_runtime.h>
#include <cuda_fp16.h>
#include <cstdint>

#define SEQ 1024
#define DIM 128
#define NG 64

__device__ __half g_qh0[(size_t)NG*SEQ*DIM];
__device__ __half g_qh1[(size_t)NG*SEQ*DIM];
__device__ __half g_kh0[(size_t)NG*SEQ*DIM];
__device__ __half g_kh1[(size_t)NG*SEQ*DIM];
__device__ __half g_vh0[(size_t)NG*SEQ*DIM];
__device__ __half g_oh [(size_t)NG*SEQ*DIM];

// ---------------- helpers ----------------
__device__ __forceinline__ uint32_t s2u(const void* p){
    uint32_t a; asm("{ .reg .u64 t; cvta.to.shared.u64 t,%1; cvt.u32.u64 %0,t; }":"=r"(a):"l"(p)); return a;
}
__device__ __forceinline__ void cpa16(uint32_t d, const void* s){
    asm volatile("cp.async.cg.shared.global [%0],[%1],16;"::"r"(d),"l"(s));
}
#define CPCOMMIT() asm volatile("cp.async.commit_group;":::"memory")
#define CPWAIT1()  asm volatile("cp.async.wait_group 1;":::"memory")
#define CPWAIT0()  asm volatile("cp.async.wait_group 0;":::"memory")

__device__ __forceinline__ void ldm4(uint32_t r[4], uint32_t a){
    asm volatile("ldmatrix.sync.aligned.m8n8.x4.shared.b16 {%0,%1,%2,%3},[%4];"
        :"=r"(r[0]),"=r"(r[1]),"=r"(r[2]),"=r"(r[3]):"r"(a));
}
__device__ __forceinline__ void ldm4t(uint32_t r[4], uint32_t a){
    asm volatile("ldmatrix.sync.aligned.m8n8.x4.trans.shared.b16 {%0,%1,%2,%3},[%4];"
        :"=r"(r[0]),"=r"(r[1]),"=r"(r[2]),"=r"(r[3]):"r"(a));
}
__device__ __forceinline__ void mmaf(float c[4], const uint32_t a[4], uint32_t b0, uint32_t b1){
    asm volatile("mma.sync.aligned.m16n8k16.row.col.f32.f16.f16.f32 "
        "{%0,%1,%2,%3},{%4,%5,%6,%7},{%8,%9},{%0,%1,%2,%3};"
        :"+f"(c[0]),"+f"(c[1]),"+f"(c[2]),"+f"(c[3])
        :"r"(a[0]),"r"(a[1]),"r"(a[2]),"r"(a[3]),"r"(b0),"r"(b1));
}
__device__ __forceinline__ uint32_t pkh(float a, float b){
    __half2 h = __floats2half2_rn(a,b); return *(uint32_t*)&h;
}
__device__ __forceinline__ float fex2(float x){
    x = fmaxf(x, -120.f);
    float xf = floorf(x), f = x - xf;
    float p = fmaf(f, 0.0013333558f, 0.0096181291f);
    p = fmaf(f, p, 0.0555041087f);
    p = fmaf(f, p, 0.2402265070f);
    p = fmaf(f, p, 0.6931471806f);
    p = fmaf(f, p, 1.0f);
    return __int_as_float(((int)xf + 127) << 23) * p;
}
#define SWZH(r,d) ((r)*128 + ((((d)>>3)^((r)&7))<<3) + ((d)&7))

__device__ __forceinline__ void split_store(__half* sm, uint32_t offH, uint32_t offL, float4 t){
    __half2 h01=__floats2half2_rn(t.x,t.y), h23=__floats2half2_rn(t.z,t.w);
    float2 f01=__half22float2(h01), f23=__half22float2(h23);
    __half2 l01=__floats2half2_rn(t.x-f01.x,t.y-f01.y), l23=__floats2half2_rn(t.z-f23.x,t.w-f23.y);
    *(uint32_t*)((char*)sm+offH)  =*(uint32_t*)&h01;
    *(uint32_t*)((char*)sm+offH+4)=*(uint32_t*)&h23;
    *(uint32_t*)((char*)sm+offL)  =*(uint32_t*)&l01;
    *(uint32_t*)((char*)sm+offL+4)=*(uint32_t*)&l23;
}

// ================= Kernel 1a: Q/K projections, 64-row tiles (R9, best) ======
#define PROJQK_SMEM 98304
__global__ void __launch_bounds__(256,2) proj_qk_kernel(
    const float* __restrict__ Xq, const float* __restrict__ Xk,
    const float* __restrict__ Wq, const float* __restrict__ Wk)
{
    extern __shared__ __half sm[];
    const uint32_t sb=s2u(sm);
    const int z=blockIdx.z, mat=z>>3, bm=z&7, m=bm&3;
    const float* X=(mat? Xk:Xq)+(size_t)bm*SEQ*DIM;
    const float* W=(mat? Wk:Wq)+(size_t)m*DIM*(8*DIM);
    const int tid=threadIdx.x, warp=tid>>5, lane=tid&31;
    const int bx=blockIdx.x, by=blockIdx.y;
    const int wm=warp&3, wn=warp>>2;
    const int lr=(lane&7)+((lane>>3)&1)*8;
    const int ldd=((lane>>4)&1)*8;

#pragma unroll
    for(int i=0;i<8;i++){
        int idx=tid+i*256, row=idx>>5, c4=(idx&31)*4;
        float4 xv=*(const float4*)(X+(size_t)(by*64+row)*DIM+c4);
        uint32_t xo=2*SWZH(row,c4);
        split_store(sm, xo, 16384+xo, xv);
    }
#pragma unroll
    for(int i=0;i<16;i++){
        int idx=tid+i*256, row=idx>>5, c4=(idx&31)*4;
        float4 wv=*(const float4*)(W+(size_t)row*(8*DIM)+bx*128+c4);
        uint32_t wo=2*SWZH(row,c4);
        split_store(sm, 32768+wo, 65536+wo, wv);
    }
    __syncthreads();

    float acc[8][4];
#pragma unroll
    for(int j=0;j<8;j++)
#pragma unroll
        for(int p2=0;p2<4;p2++) acc[j][p2]=0.f;

#pragma unroll
    for(int kc=0;kc<8;kc++){
        uint32_t ah[4], al[4];
        ldm4(ah, sb+2*(SWZH(wm*16+lr, kc*16+ldd)));
        ldm4(al, sb+2*(8192+SWZH(wm*16+lr, kc*16+ldd)));
#pragma unroll
        for(int np=0;np<4;np++){
            uint32_t wh[4], wl[4];
            ldm4t(wh, sb+2*(16384+SWZH(kc*16+lr, wn*64+np*16+ldd)));
            ldm4t(wl, sb+2*(32768+SWZH(kc*16+lr, wn*64+np*16+ldd)));
            mmaf(acc[2*np],ah,wh[0],wh[1]); mmaf(acc[2*np+1],ah,wh[2],wh[3]);
            mmaf(acc[2*np],ah,wl[0],wl[1]); mmaf(acc[2*np+1],ah,wl[2],wl[3]);
            mmaf(acc[2*np],al,wh[0],wh[1]); mmaf(acc[2*np+1],al,wh[2],wh[3]);
        }
    }

    const int g=bm*8+bx;
    __half* d0 = mat? g_kh0 : g_qh0;
    __half* d1 = mat? g_kh1 : g_qh1;
    const float sc = mat? 1.f : 0.12753102001968606f;   // log2(e)/sqrt(128)
    const int rbase=by*64+wm*16+(lane>>2);
    const int dbase=wn*64+2*(lane&3);
#pragma unroll
    for(int j=0;j<8;j++)
#pragma unroll
        for(int hr=0;hr<2;hr++){
            int r=rbase+hr*8, d=dbase+j*8;
            float x0=acc[j][2*hr]*sc, x1=acc[j][2*hr+1]*sc;
            __half2 h=__floats2half2_rn(x0,x1);
            size_t off=((size_t)(g*SEQ)+r)*DIM+d;
            *(__half2*)(d0+off)=h;
            float2 hf=__half22float2(h);
            *(__half2*)(d1+off)=__floats2half2_rn(x0-hf.x,x1-hf.y);
        }
}

// ================= Kernel 1b: V projection, hh-only, 64-row tiles (R9) ======
#define PROJV_SMEM 49152
__global__ void __launch_bounds__(256,2) proj_v_kernel(
    const float* __restrict__ Xv, const float* __restrict__ Wv)
{
    extern __shared__ __half sm[];
    const uint32_t sb=s2u(sm);
    const int bm=blockIdx.z, m=bm&3;
    const float* X=Xv+(size_t)bm*SEQ*DIM;
    const float* W=Wv+(size_t)m*DIM*(8*DIM);
    const int tid=threadIdx.x, warp=tid>>5, lane=tid&31;
    const int bx=blockIdx.x, by=blockIdx.y;
    const int wm=warp&3, wn=warp>>2;
    const int lr=(lane&7)+((lane>>3)&1)*8;
    const int ldd=((lane>>4)&1)*8;

#pragma unroll
    for(int i=0;i<8;i++){
        int idx=tid+i*256, row=idx>>5, c4=(idx&31)*4;
        float4 t=*(const float4*)(X+(size_t)(by*64+row)*DIM+c4);
        __half2 h01=__floats2half2_rn(t.x,t.y), h23=__floats2half2_rn(t.z,t.w);
        uint32_t xo=2*SWZH(row,c4);
        *(uint32_t*)((char*)sm+xo)=*(uint32_t*)&h01; *(uint32_t*)((char*)sm+xo+4)=*(uint32_t*)&h23;
    }
#pragma unroll
    for(int i=0;i<16;i++){
        int idx=tid+i*256, row=idx>>5, c4=(idx&31)*4;
        float4 t=*(const float4*)(W+(size_t)row*(8*DIM)+bx*128+c4);
        __half2 h01=__floats2half2_rn(t.x,t.y), h23=__floats2half2_rn(t.z,t.w);
        uint32_t wo=2*SWZH(row,c4);
        *(uint32_t*)((char*)sm+16384+wo)=*(uint32_t*)&h01; *(uint32_t*)((char*)sm+16384+wo+4)=*(uint32_t*)&h23;
    }
    __syncthreads();

    float acc[8][4];
#pragma unroll
    for(int j=0;j<8;j++)
#pragma unroll
        for(int p2=0;p2<4;p2++) acc[j][p2]=0.f;

#pragma unroll
    for(int kc=0;kc<8;kc++){
        uint32_t ah[4];
        ldm4(ah, sb+2*(SWZH(wm*16+lr, kc*16+ldd)));
#pragma unroll
        for(int np=0;np<4;np++){
            uint32_t wh[4];
            ldm4t(wh, sb+2*(8192+SWZH(kc*16+lr, wn*64+np*16+ldd)));
            mmaf(acc[2*np],ah,wh[0],wh[1]); mmaf(acc[2*np+1],ah,wh[2],wh[3]);
        }
    }

    const int g=bm*8+bx;
    const int rbase=by*64+wm*16+(lane>>2);
    const int dbase=wn*64+2*(lane&3);
#pragma unroll
    for(int j=0;j<8;j++)
#pragma unroll
        for(int hr=0;hr<2;hr++){
            int r=rbase+hr*8, d=dbase+j*8;
            size_t off=((size_t)(g*SEQ)+r)*DIM+d;
            *(__half2*)(g_vh0+off)=__floats2half2_rn(acc[j][2*hr],acc[j][2*hr+1]);
        }
}

// ================= Kernel 2: flash attention (R9 + fused prologue) ==========
// half-index map: buf b at b*24576: Kh | Kl(+8192) | Vh(+16384)  [96 KB]
//                 Qh staged at 49152 [16 KB]; Ql staged in buf1.Vh (40960)
// total 112 KB, 2 CTAs/SM.
#define ATTN_SMEM 114688

__device__ __forceinline__ void load_kv(uint32_t sb, size_t gbase, int t, int buf, int tid){
#pragma unroll
    for(int i=0;i<24;i++){
        int idx=tid+i*128, arr=idx>>10, rem=idx&1023, row=rem>>4, ch=rem&15;
        const __half* src;
        if(arr==0) src=g_kh0; else if(arr==1) src=g_kh1; else src=g_vh0;
        src += gbase+(size_t)(t*64+row)*DIM+ch*8;
        uint32_t dst=sb+2*(buf*24576+arr*8192+SWZH(row,ch*8));
        cpa16(dst,src);
    }
}

__global__ void __launch_bounds__(128,2) attn_kernel()
{
    extern __shared__ __half sm[];
    const uint32_t sb=s2u(sm);
    const int tid=threadIdx.x, warp=tid>>5, lane=tid&31;
    const int g=blockIdx.y, qt=blockIdx.x;
    const size_t gbase=(size_t)g*SEQ*DIM;
    const int lr=(lane&7)+((lane>>3)&1)*8;
    const int ldd=((lane>>4)&1)*8;

    // group 0: Q (Qh->49152, Ql->buf1.Vh@40960) + kv0 concurrently
#pragma unroll
    for(int i=0;i<16;i++){
        int idx=tid+i*128, arr=idx>>10, rem=idx&1023, row=rem>>4, ch=rem&15;
        const __half* src=(arr? g_qh1:g_qh0)+gbase+(size_t)(qt*64+row)*DIM+ch*8;
        cpa16(sb+2*((arr?40960:49152)+SWZH(row,ch*8)), src);
    }
    load_kv(sb,gbase,0,0,tid);
    CPCOMMIT();
    CPWAIT0();
    __syncthreads();
    uint32_t qah[8][4], qal[8][4];
#pragma unroll
    for(int kc=0;kc<8;kc++){
        ldm4(qah[kc], sb+2*(49152+SWZH(warp*16+lr, kc*16+ldd)));
        ldm4(qal[kc], sb+2*(40960+SWZH(warp*16+lr, kc*16+ldd)));
    }
    __syncthreads();   // Ql read by all warps before kv1 overwrites buf1.Vh

    load_kv(sb,gbase,1,1,tid); CPCOMMIT();   // g1, lands during tile-0 compute

    float o[16][4];
#pragma unroll
    for(int i=0;i<16;i++)
#pragma unroll
        for(int j2=0;j2<4;j2++) o[i][j2]=0.f;
    float mA=-1e30f, mB=-1e30f, lA=0.f, lB=0.f;

    for(int t=0;t<16;t++){
        if(t>0){
            if(t<15) CPWAIT1(); else CPWAIT0();
            __syncthreads();
        }
        const uint32_t KHB=(t&1)*24576, KLB=KHB+8192, VHB=KHB+16384;

        float c[8][4];
#pragma unroll
        for(int j=0;j<8;j++)
#pragma unroll
            for(int i2=0;i2<4;i2++) c[j][i2]=0.f;
#pragma unroll
        for(int kc=0;kc<8;kc++){
#pragma unroll
            for(int np=0;np<4;np++){
                uint32_t kh[4],kl[4];
                ldm4(kh, sb+2*(KHB+SWZH(np*16+lr, kc*16+ldd)));
                ldm4(kl, sb+2*(KLB+SWZH(np*16+lr, kc*16+ldd)));
                mmaf(c[2*np],qah[kc],kh[0],kh[2]); mmaf(c[2*np+1],qah[kc],kh[1],kh[3]);
                mmaf(c[2*np],qah[kc],kl[0],kl[2]); mmaf(c[2*np+1],qah[kc],kl[1],kl[3]);
                mmaf(c[2*np],qal[kc],kh[0],kh[2]); mmaf(c[2*np+1],qal[kc],kh[1],kh[3]);
            }
        }

        float tA=-1e30f, tB=-1e30f;
#pragma unroll
        for(int j=0;j<8;j++){
            tA=fmaxf(tA,fmaxf(c[j][0],c[j][1]));
            tB=fmaxf(tB,fmaxf(c[j][2],c[j][3]));
        }
        tA=fmaxf(tA,__shfl_xor_sync(0xffffffffu,tA,1));
        tA=fmaxf(tA,__shfl_xor_sync(0xffffffffu,tA,2));
        tB=fmaxf(tB,__shfl_xor_sync(0xffffffffu,tB,1));
        tB=fmaxf(tB,__shfl_xor_sync(0xffffffffu,tB,2));
        float mnA=fmaxf(mA,tA), mnB=fmaxf(mB,tB);
        float cA=fex2(mA-mnA), cB=fex2(mB-mnB);
        mA=mnA; mB=mnB;
        uint32_t pa[8], pb[8];
        float sA=0.f, sB=0.f;
#pragma unroll
        for(int j=0;j<8;j++){
            float p0=fex2(c[j][0]-mnA), p1=fex2(c[j][1]-mnA);
            float p2=fex2(c[j][2]-mnB), p3=fex2(c[j][3]-mnB);
            sA+=p0+p1; sB+=p2+p3;
            pa[j]=pkh(p0,p1); pb[j]=pkh(p2,p3);
        }
        lA=lA*cA+sA; lB=lB*cB+sB;
        if(cA!=1.f){
#pragma unroll
            for(int dt=0;dt<16;dt++){ o[dt][0]*=cA; o[dt][1]*=cA; }
        }
        if(cB!=1.f){
#pragma unroll
            for(int dt=0;dt<16;dt++){ o[dt][2]*=cB; o[dt][3]*=cB; }
        }

#pragma unroll
        for(int kc=0;kc<4;kc++){
            uint32_t a4[4]={pa[2*kc],pb[2*kc],pa[2*kc+1],pb[2*kc+1]};
#pragma unroll
            for(int dp=0;dp<8;dp++){
                uint32_t vh[4];
                ldm4t(vh, sb+2*(VHB+SWZH(kc*16+lr, dp*16+ldd)));
                mmaf(o[2*dp],a4,vh[0],vh[1]); mmaf(o[2*dp+1],a4,vh[2],vh[3]);
            }
        }
        __syncthreads();
        if(t+2<16){ load_kv(sb,gbase,t+2,t&1,tid); CPCOMMIT(); }
    }

    lA+=__shfl_xor_sync(0xffffffffu,lA,1); lA+=__shfl_xor_sync(0xffffffffu,lA,2);
    lB+=__shfl_xor_sync(0xffffffffu,lB,1); lB+=__shfl_xor_sync(0xffffffffu,lB,2);
    float iA=1.f/lA, iB=1.f/lB;
    int rA=qt*64+warp*16+(lane>>2), rB=rA+8, dc=2*(lane&3);
    __half* obase=g_oh+gbase;
#pragma unroll
    for(int dt=0;dt<16;dt++){
        *(__half2*)(obase+(size_t)rA*DIM+dt*8+dc)=__floats2half2_rn(o[dt][0]*iA,o[dt][1]*iA);
        *(__half2*)(obase+(size_t)rB*DIM+dt*8+dc)=__floats2half2_rn(o[dt][2]*iB,o[dt][3]*iB);
    }
}

// ================= Kernel 3: head-mean + residual ===========================
__global__ void __launch_bounds__(256) reduce_kernel(const float* __restrict__ q, float* __restrict__ out)
{
    int i4=blockIdx.x*256+threadIdx.x;
    int bm=i4>>15, r4=i4&32767;
    float sx=0,sy=0,sz=0,sw=0;
#pragma unroll
    for(int h=0;h<8;h++){
        uint2 v=*(const uint2*)(g_oh+((size_t)(bm*8+h))*131072+(size_t)r4*4);
        __half2 a=*(__half2*)&v.x, b=*(__half2*)&v.y;
        float2 fa=__half22float2(a), fb=__half22float2(b);
        sx+=fa.x; sy+=fa.y; sz+=fb.x; sw+=fb.y;
    }
    float4 qv=((const float4*)q)[i4];
    ((float4*)out)[i4]=make_float4(qv.x+0.125f*sx,qv.y+0.125f*sy,qv.z+0.125f*sz,qv.w+0.125f*sw);
}

extern "C" void kernel_launch(void* const* d_in, const int* in_sizes, int n_in,
                              void* d_out, int out_size)
{
    const float *q=(const float*)d_in[0], *k=(const float*)d_in[1], *v=(const float*)d_in[2];
    const float *Wq=(const float*)d_in[3], *Wk=(const float*)d_in[4], *Wv=(const float*)d_in[5];
    float* out=(float*)d_out;
    cudaFuncSetAttribute(proj_qk_kernel, cudaFuncAttributeMaxDynamicSharedMemorySize, PROJQK_SMEM);
    cudaFuncSetAttribute(proj_v_kernel, cudaFuncAttributeMaxDynamicSharedMemorySize, PROJV_SMEM);
    cudaFuncSetAttribute(attn_kernel, cudaFuncAttributeMaxDynamicSharedMemorySize, ATTN_SMEM);
    proj_qk_kernel<<<dim3(8,16,16),256,PROJQK_SMEM>>>(q,k,Wq,Wk);
    proj_v_kernel <<<dim3(8,16,8),256,PROJV_SMEM>>>(v,Wv);
    attn_kernel<<<dim3(16,64),128,ATTN_SMEM>>>();
    reduce_kernel<<<1024,256>>>(q,out);
}